// round 1
// baseline (speedup 1.0000x reference)
#include <cuda_runtime.h>

// Problem constants
#define B_   4
#define N_   24
#define C_   256
#define H_   100
#define W_   100
#define OUT_ 7
#define P_   276                    // N*(N-1)/2
#define CH_  (C_ * OUT_ * OUT_)     // 12544 floats per [C,7,7] chunk
#define HW_  (H_ * W_)
#define SCALE_ 0.25f

// NHWC scratch for features (allowed: __device__ global, no runtime alloc)
__device__ float g_nhwc[(size_t)B_ * HW_ * C_];

// ---------------------------------------------------------------------------
// Kernel 1: NCHW -> NHWC transpose. Per batch: transpose [C, HW] -> [HW, C].
// blockDim (32,8), 32x32 tiles with +1 padding. Both sides coalesced.
// ---------------------------------------------------------------------------
__global__ void nchw_to_nhwc_kernel(const float* __restrict__ in) {
    __shared__ float tile[32][33];
    const int b   = blockIdx.z;
    const int c0  = blockIdx.y * 32;   // C_=256 multiple of 32, no bounds needed on c
    const int hw0 = blockIdx.x * 32;
    const int tx = threadIdx.x, ty = threadIdx.y;

    const float* src = in + (size_t)b * C_ * HW_;
#pragma unroll
    for (int i = 0; i < 32; i += 8) {
        const int c  = c0 + ty + i;
        const int hw = hw0 + tx;
        float v = 0.0f;
        if (hw < HW_) v = src[(size_t)c * HW_ + hw];
        tile[ty + i][tx] = v;
    }
    __syncthreads();

    float* dst = g_nhwc + (size_t)b * HW_ * C_;
#pragma unroll
    for (int i = 0; i < 32; i += 8) {
        const int hw = hw0 + ty + i;
        const int c  = c0 + tx;
        if (hw < HW_) dst[(size_t)hw * C_ + c] = tile[tx][ty + i];
    }
}

// ---------------------------------------------------------------------------
// Kernel 2: one CTA per roi (objects first, then unions).
//  Phase A: decode roi box (object box or pair union) + separable bilinear
//           sample tables (14 y-samples, 14 x-samples).
//  Phase B: compute pooled [C,7,7] into SMEM. Thread (c4 = tid&63) covers 4
//           consecutive channels via float4; (slot = tid>>6) strides the 49
//           bins. All feature loads are coalesced 512B-per-warp from NHWC.
//  Phase C: coalesced float4 fan-out copy of the 50KB tile to every output
//           destination (object m -> all pairs containing m; union -> slot 2).
// ---------------------------------------------------------------------------
__global__ __launch_bounds__(256, 4) void roi_pair_kernel(
    const float* __restrict__ boxes,   // [B, N, 4] xyxy, image coords
    float* __restrict__ out)           // [B*P, 3, C, 7, 7]
{
    __shared__ __align__(16) float pooled[CH_];
    __shared__ int   sy0[14], sy1[14], sx0[14], sx1[14];
    __shared__ float sly[14], shy[14], slx[14], shx[14];
    __shared__ float roi[4];

    const int bid = blockIdx.x;
    const int tid = threadIdx.x;

    int b, m;  // batch, roi index within batch (m < N_: object, else union pair m-N_)
    if (bid < B_ * N_) { b = bid / N_; m = bid % N_; }
    else { const int u = bid - B_ * N_; b = u / P_; m = N_ + (u % P_); }

    if (tid == 0) {
        float x1, y1, x2, y2;
        if (m < N_) {
            const float* bx = boxes + ((size_t)b * N_ + m) * 4;
            x1 = bx[0]; y1 = bx[1]; x2 = bx[2]; y2 = bx[3];
        } else {
            int p = m - N_;
            int i = 0, rem = p, cnt = N_ - 1;
            while (rem >= cnt) { rem -= cnt; ++i; --cnt; }
            const int j = i + 1 + rem;
            const float* ba = boxes + ((size_t)b * N_ + i) * 4;
            const float* bb = boxes + ((size_t)b * N_ + j) * 4;
            x1 = fminf(ba[0], bb[0]);
            y1 = fminf(ba[1], bb[1]);
            x2 = fmaxf(ba[2], bb[2]);
            y2 = fmaxf(ba[3], bb[3]);
        }
        roi[0] = x1; roi[1] = y1; roi[2] = x2; roi[3] = y2;
    }
    __syncthreads();

    // Separable sample tables: tid 0..13 -> x dimension, tid 14..27 -> y.
    if (tid < 28) {
        const int  d   = tid % 14;
        const bool isY = (tid >= 14);
        const float c1 = (isY ? roi[1] : roi[0]) * SCALE_;
        const float c2 = (isY ? roi[3] : roi[2]) * SCALE_;
        const float sz   = fmaxf(c2 - c1, 1.0f);
        const float bsz  = sz * (1.0f / OUT_);
        // grid g = bin + (sub + 0.5)/2, d = 2*bin + sub
        const float g = (float)(d >> 1) + ((float)(d & 1) + 0.5f) * 0.5f;
        const float X = c1 + g * bsz;
        const int   lim = isY ? H_ : W_;
        const bool  valid = (X > -1.0f) && (X < (float)lim);
        const float Xc  = fminf(fmaxf(X, 0.0f), (float)(lim - 1));
        const float x0f = floorf(Xc);
        float lx = Xc - x0f;
        float hx = 1.0f - lx;
        if (!valid) { lx = 0.0f; hx = 0.0f; }
        const int x0  = (int)x0f;
        const int x1i = min(x0 + 1, lim - 1);
        if (isY) { sy0[d] = x0; sy1[d] = x1i; sly[d] = lx; shy[d] = hx; }
        else     { sx0[d] = x0; sx1[d] = x1i; slx[d] = lx; shx[d] = hx; }
    }
    __syncthreads();

    // Phase B: pooled compute.
    const int c4   = tid & 63;   // float4 channel group: channels 4*c4 .. 4*c4+3
    const int slot = tid >> 6;   // 0..3
    const float4* __restrict__ feat =
        reinterpret_cast<const float4*>(g_nhwc) + (size_t)b * HW_ * (C_ / 4);

    for (int bin = slot; bin < OUT_ * OUT_; bin += 4) {
        const int py = bin / OUT_;
        const int px = bin - py * OUT_;
        float4 acc = make_float4(0.f, 0.f, 0.f, 0.f);
#pragma unroll
        for (int sy = 0; sy < 2; ++sy) {
            const int   yi = 2 * py + sy;
            const int   y0 = sy0[yi], y1 = sy1[yi];
            const float ly = sly[yi], hy = shy[yi];
            const int r0 = y0 * W_;
            const int r1 = y1 * W_;
#pragma unroll
            for (int sx = 0; sx < 2; ++sx) {
                const int   xi = 2 * px + sx;
                const int   x0 = sx0[xi], x1 = sx1[xi];
                const float lx = slx[xi], hx = shx[xi];
                const float4 f00 = feat[(size_t)(r0 + x0) * 64 + c4];
                const float4 f01 = feat[(size_t)(r0 + x1) * 64 + c4];
                const float4 f10 = feat[(size_t)(r1 + x0) * 64 + c4];
                const float4 f11 = feat[(size_t)(r1 + x1) * 64 + c4];
                const float w00 = hy * hx, w01 = hy * lx, w10 = ly * hx, w11 = ly * lx;
                acc.x += w00 * f00.x + w01 * f01.x + w10 * f10.x + w11 * f11.x;
                acc.y += w00 * f00.y + w01 * f01.y + w10 * f10.y + w11 * f11.y;
                acc.z += w00 * f00.z + w01 * f01.z + w10 * f10.z + w11 * f11.z;
                acc.w += w00 * f00.w + w01 * f01.w + w10 * f10.w + w11 * f11.w;
            }
        }
        // mean over 4 samples
        const int base = (4 * c4) * 49 + bin;
        pooled[base]       = acc.x * 0.25f;
        pooled[base + 49]  = acc.y * 0.25f;
        pooled[base + 98]  = acc.z * 0.25f;
        pooled[base + 147] = acc.w * 0.25f;
    }
    __syncthreads();

    // Phase C: fan-out copy (float4, fully coalesced).
    const float4* __restrict__ psrc = reinterpret_cast<const float4*>(pooled);
    const int NV = CH_ / 4;  // 3136
    if (m < N_) {
        // slot 0: pairs (m, j>m); slot 1: pairs (i<m, m)
        for (int j = m + 1; j < N_; ++j) {
            const int p = m * (N_ - 1) - (m * (m - 1)) / 2 + (j - m - 1);
            float4* dst = reinterpret_cast<float4*>(out) +
                          (((size_t)b * P_ + p) * 3 + 0) * NV;
            for (int idx = tid; idx < NV; idx += 256) dst[idx] = psrc[idx];
        }
        for (int i = 0; i < m; ++i) {
            const int p = i * (N_ - 1) - (i * (i - 1)) / 2 + (m - i - 1);
            float4* dst = reinterpret_cast<float4*>(out) +
                          (((size_t)b * P_ + p) * 3 + 1) * NV;
            for (int idx = tid; idx < NV; idx += 256) dst[idx] = psrc[idx];
        }
    } else {
        const int p = m - N_;
        float4* dst = reinterpret_cast<float4*>(out) +
                      (((size_t)b * P_ + p) * 3 + 2) * NV;
        for (int idx = tid; idx < NV; idx += 256) dst[idx] = psrc[idx];
    }
}

// ---------------------------------------------------------------------------
extern "C" void kernel_launch(void* const* d_in, const int* in_sizes, int n_in,
                              void* d_out, int out_size) {
    const float* features = (const float*)d_in[0];  // [B,C,H,W] float32
    const float* boxes    = (const float*)d_in[1];  // [B,N,4]   float32
    float* out = (float*)d_out;

    dim3 tgrid((HW_ + 31) / 32, C_ / 32, B_);
    nchw_to_nhwc_kernel<<<tgrid, dim3(32, 8)>>>(features);

    const int nblocks = B_ * N_ + B_ * P_;  // 96 object CTAs first, then 1104 unions
    roi_pair_kernel<<<nblocks, 256>>>(boxes, out);
}